// round 10
// baseline (speedup 1.0000x reference)
#include <cuda_runtime.h>
#include <cstddef>

#define SEQ   512
#define BATCH 4096
#define INDIM 9
#define HID   64
#define OUTD  10
#define NTH   384                       // 12 warps: 0-3 L1, 4-7 L2, 8-11 pI
#define BLKS  16                        // steps per phase
#define NBLK  (SEQ/BLKS)                // 32
#define NPH   (NBLK + 2)                // 34 phases
#define RING  32                        // ring rows (2 blocks)
#define CSCALE 2.885390081777927f       // 2/ln2
#define WSCALE (-2.0f * CSCALE)

// shared memory float offsets
#define O_HIST  0                          // SEQ*HID : xw' -> r2 history
#define O_XS    (O_HIST + SEQ*HID)         // SEQ*INDIM
#define O_RING  (O_XS + SEQ*INDIM)         // RING*HID   r1 ring
#define O_PIH   (O_RING + RING*HID)        // RING*128   pI half-partials
#define O_R2    (O_PIH + RING*128)         // 2*HID      r2 double buffer
#define O_RS1   (O_R2 + 2*HID)             // HID
#define O_WFC   (O_RS1 + HID)              // OUTD*HID (scaled -2)
#define O_BFC   (O_WFC + OUTD*HID)         // 16
#define SM_FLOATS (O_BFC + 16)
#define SM_BYTES  (SM_FLOATS * 4)

typedef unsigned long long ull;

__device__ __forceinline__ ull ffma2(ull a, ull b, ull c) {
    ull d; asm("fma.rn.f32x2 %0, %1, %2, %3;" : "=l"(d) : "l"(a), "l"(b), "l"(c));
    return d;
}
__device__ __forceinline__ ull fadd2(ull a, ull b) {
    ull d; asm("add.rn.f32x2 %0, %1, %2;" : "=l"(d) : "l"(a), "l"(b));
    return d;
}
__device__ __forceinline__ float f2sum(ull a) {
    float2 f = *reinterpret_cast<float2*>(&a);
    return f.x + f.y;
}
__device__ __forceinline__ ull pack2(float x, float y) {
    ull r; asm("mov.b64 %0, {%1,%2};" : "=l"(r) : "f"(x), "f"(y));
    return r;
}
// r = 1/(e^{2s}+1) with input pre-scaled by 2/ln2; tanh(s) = 1 - 2r
__device__ __forceinline__ float sig_r(float in) {
    float e, r;
    asm("ex2.approx.f32 %0, %1;" : "=f"(e) : "f"(in));
    asm("rcp.approx.f32 %0, %1;" : "=f"(r) : "f"(e + 1.0f));
    return r;
}
#define BAR_L1() asm volatile("bar.sync 1, 128;" ::: "memory")
#define BAR_L2() asm volatile("bar.sync 2, 128;" ::: "memory")

// 32-long half dot: 8 LDS.128, 16 FFMA2 (4 accums, depth 4) -> float
__device__ __forceinline__ float halfdot(const ull* __restrict__ w,
                                         const float* __restrict__ src) {
    const ulonglong2* hp = reinterpret_cast<const ulonglong2*>(src);
    ull a0 = 0ull, a1 = 0ull, a2 = 0ull, a3 = 0ull;
    #pragma unroll
    for (int q = 0; q < 4; ++q) {
        ulonglong2 u = hp[2*q], v = hp[2*q+1];
        a0 = ffma2(u.x, w[4*q+0], a0);
        a1 = ffma2(u.y, w[4*q+1], a1);
        a2 = ffma2(v.x, w[4*q+2], a2);
        a3 = ffma2(v.y, w[4*q+3], a3);
    }
    return f2sum(fadd2(fadd2(a0, a1), fadd2(a2, a3)));
}

// load 32 scaled weights (cols [32h, 32h+32) of row u) into 16 ull; also raw rowsum of that half
__device__ __forceinline__ float load_whalf(const float* __restrict__ W, int u, int off,
                                            ull* __restrict__ w) {
    const float4* p = reinterpret_cast<const float4*>(W + (size_t)u * HID + off);
    float s = 0.f;
    #pragma unroll
    for (int q = 0; q < 8; ++q) {
        float4 v = p[q];
        s += (v.x + v.y) + (v.z + v.w);
        w[2*q]   = pack2(v.x*WSCALE, v.y*WSCALE);
        w[2*q+1] = pack2(v.z*WSCALE, v.w*WSCALE);
    }
    return s;
}

__global__ __launch_bounds__(NTH, 1)
void rnn_motion_kernel(const float* __restrict__ x,
                       const float* __restrict__ Wih0, const float* __restrict__ Whh0,
                       const float* __restrict__ bih0, const float* __restrict__ bhh0,
                       const float* __restrict__ Wih1, const float* __restrict__ Whh1,
                       const float* __restrict__ bih1, const float* __restrict__ bhh1,
                       const float* __restrict__ Wfc,  const float* __restrict__ bfc_g,
                       float* __restrict__ out)
{
    extern __shared__ float sm[];
    float* hist = sm + O_HIST;
    float* xs   = sm + O_XS;
    float* ring = sm + O_RING;
    float* pih  = sm + O_PIH;
    float* r2b  = sm + O_R2;
    float* rs1  = sm + O_RS1;
    float* wfc  = sm + O_WFC;
    float* bfc  = sm + O_BFC;

    const int tid  = threadIdx.x;
    const int wid  = tid >> 5;
    const int lane = tid & 31;
    const int u    = ((wid & 3) << 4) | (lane & 15);  // unit 0..63 within role group
    const int h    = lane >> 4;                        // half 0/1
    const int off  = h << 5;                           // 0 or 32

    // ---- prologue A ----
    for (int e = tid; e < SEQ*INDIM; e += NTH) {
        int t = e / INDIM, k = e % INDIM;
        xs[e] = x[((size_t)t * BATCH + (BATCH - 1)) * INDIM + k];
    }
    for (int e = tid; e < OUTD*HID; e += NTH) wfc[e] = -2.0f * Wfc[e];
    if (tid < HID) {
        ring[(RING-1)*HID + tid] = 0.5f;    // r1(-1): h=0 <-> r=0.5
        r2b[HID + tid]           = 0.5f;    // r2(-1), parity 1
        const float4* p = reinterpret_cast<const float4*>(Whh0 + (size_t)tid * HID);
        float s = 0.f;
        #pragma unroll
        for (int q = 0; q < 16; ++q) { float4 v = p[q]; s += (v.x+v.y)+(v.z+v.w); }
        rs1[tid] = s;                       // rowsum(Whh0_i)
    }
    if (tid < OUTD) {                       // bfc'[o] = bfc + rowsum(Wfc_o)
        const float4* p = reinterpret_cast<const float4*>(Wfc + (size_t)tid * HID);
        float s = bfc_g[tid];
        #pragma unroll
        for (int q = 0; q < 16; ++q) { float4 v = p[q]; s += (v.x+v.y)+(v.z+v.w); }
        bfc[tid] = s;
    }
    __syncthreads();

    // ---- prologue B: xw'[t][i] = C*(x_t.Wih0_i + b_ih0 + b_hh0 + rowsum(Whh0_i)) ----
    {
        const int ii = tid & (HID-1);
        float wi[INDIM];
        #pragma unroll
        for (int k = 0; k < INDIM; ++k) wi[k] = CSCALE * Wih0[ii*INDIM + k];
        const float bb = CSCALE * (bih0[ii] + bhh0[ii] + rs1[ii]);
        for (int t = tid >> 6; t < SEQ; t += NTH/HID) {
            float s = bb;
            #pragma unroll
            for (int k = 0; k < INDIM; ++k) s += xs[t*INDIM + k] * wi[k];
            hist[t*HID + ii] = s;
        }
    }
    __syncthreads();

    // ==================== 3-stage pipelined scan ====================
    if (wid < 4) {
        // ===== L1 quad: lane owns half h of unit u; 16 FFMA2/step =====
        ull w1[16];
        (void)load_whalf(Whh0, u, off, w1);
        for (int m = 0; m < NPH; ++m) {
            if (m < NBLK) {
                const int t0 = m * BLKS;
                const float* src = ring + ((t0 - 1) & (RING-1)) * HID;
                float*       dst = ring + (t0 & (RING-1)) * HID;
                const float* xwp = hist + t0*HID + u;
                #pragma unroll 2
                for (int j = 0; j < BLKS; ++j) {
                    float p = halfdot(w1, src + off);
                    p += __shfl_xor_sync(0xffffffffu, p, 16);
                    float r = sig_r(p + *xwp);
                    dst[u] = r;                 // both halves: same value, benign
                    BAR_L1();
                    src = dst; dst += HID; xwp += HID;
                }
            }
            __syncthreads();
        }
    } else if (wid < 8) {
        // ===== L2 quad: 16 FFMA2/step + own pI half; 2 blocks behind =====
        ull wh[16];
        float rsH = load_whalf(Whh1, u, off, wh);
        rsH += __shfl_xor_sync(0xffffffffu, rsH, 16);
        float rsI;
        {
            const float4* p = reinterpret_cast<const float4*>(Wih1 + (size_t)u * HID + off);
            float s = 0.f;
            #pragma unroll
            for (int q = 0; q < 8; ++q) { float4 v = p[q]; s += (v.x+v.y)+(v.z+v.w); }
            rsI = s + __shfl_xor_sync(0xffffffffu, s, 16);
        }
        const float base2 = CSCALE * (bih1[u] + bhh1[u] + rsI + rsH);
        for (int m = 0; m < NPH; ++m) {
            if (m >= 2) {
                const int s0 = (m - 2) * BLKS;               // even
                const float* pip = pih + (s0 & (RING-1)) * 128 + 2*u + h;
                float*       hw  = hist + s0*HID + u;
                #pragma unroll 1
                for (int jj = 0; jj < BLKS/2; ++jj) {
                    {   // s even: read r2 parity 1, write parity 0
                        float p = halfdot(wh, r2b + HID + off) + *pip;
                        p += __shfl_xor_sync(0xffffffffu, p, 16);
                        float r = sig_r(p + base2);
                        r2b[u] = r; *hw = r;
                        BAR_L2();
                        pip += 128; hw += HID;
                    }
                    {   // s odd: read parity 0, write parity 1
                        float p = halfdot(wh, r2b + off) + *pip;
                        p += __shfl_xor_sync(0xffffffffu, p, 16);
                        float r = sig_r(p + base2);
                        r2b[HID + u] = r; *hw = r;
                        BAR_L2();
                        pip += 128; hw += HID;
                    }
                }
            }
            __syncthreads();
        }
    } else {
        // ===== pI quad: half-partials of Wih1 . r1, 1 block behind, no per-step sync =====
        ull wi2[16];
        (void)load_whalf(Wih1, u, off, wi2);
        for (int m = 0; m < NPH; ++m) {
            if (m >= 1 && m < NBLK + 1) {
                const int s0 = (m - 1) * BLKS;
                const float* rrow = ring + (s0 & (RING-1)) * HID + off;
                float*       pip  = pih  + (s0 & (RING-1)) * 128 + 2*u + h;
                #pragma unroll 2
                for (int j = 0; j < BLKS; ++j) {
                    *pip = halfdot(wi2, rrow);   // unreduced half; L2's shfl merges
                    rrow += HID; pip += 128;
                }
            }
            __syncthreads();
        }
    }
    __syncthreads();

    // ---- epilogue: out[t][o] = bfc'[o] + sum_k r2[t][k] * (-2*Wfc[o][k]) ----
    for (int t = tid; t < SEQ; t += NTH) {
        const float4* h4 = reinterpret_cast<const float4*>(hist + t*HID);
        #pragma unroll
        for (int o = 0; o < OUTD; ++o) {
            const float4* w4 = reinterpret_cast<const float4*>(wfc + o*HID);
            float s0 = bfc[o], s1 = 0.f, s2 = 0.f, s3 = 0.f;
            #pragma unroll
            for (int q = 0; q < HID/4; ++q) {
                float4 hv = h4[q], wv = w4[q];
                s0 = fmaf(hv.x, wv.x, s0);
                s1 = fmaf(hv.y, wv.y, s1);
                s2 = fmaf(hv.z, wv.z, s2);
                s3 = fmaf(hv.w, wv.w, s3);
            }
            out[t*OUTD + o] = (s0 + s1) + (s2 + s3);
        }
    }
}

extern "C" void kernel_launch(void* const* d_in, const int* in_sizes, int n_in,
                              void* d_out, int out_size) {
    (void)in_sizes; (void)n_in; (void)out_size;
    const float* x    = (const float*)d_in[0];
    const float* Wih0 = (const float*)d_in[1];
    const float* Whh0 = (const float*)d_in[2];
    const float* bih0 = (const float*)d_in[3];
    const float* bhh0 = (const float*)d_in[4];
    const float* Wih1 = (const float*)d_in[5];
    const float* Whh1 = (const float*)d_in[6];
    const float* bih1 = (const float*)d_in[7];
    const float* bhh1 = (const float*)d_in[8];
    const float* Wfc  = (const float*)d_in[9];
    const float* bfc  = (const float*)d_in[10];
    float* out = (float*)d_out;

    cudaFuncSetAttribute(rnn_motion_kernel,
                         cudaFuncAttributeMaxDynamicSharedMemorySize, SM_BYTES);
    rnn_motion_kernel<<<1, NTH, SM_BYTES>>>(
        x, Wih0, Whh0, bih0, bhh0, Wih1, Whh1, bih1, bhh1, Wfc, bfc, out);
}

// round 11
// speedup vs baseline: 1.2138x; 1.2138x over previous
#include <cuda_runtime.h>
#include <cstddef>

#define SEQ   512
#define BATCH 4096
#define INDIM 9
#define HID   64
#define OUTD  10
#define NTH   256                       // 8 warps: 0-3 pI (low prio), 4-5 L2, 6-7 L1
#define BLKS  16                        // steps per phase
#define NBLK  (SEQ/BLKS)                // 32
#define NPH   (NBLK + 2)                // 34 phases (3-stage pipeline)
#define RING  32                        // ring rows (2 blocks)
#define CSCALE 2.885390081777927f       // 2/ln2
#define WSCALE (-2.0f * CSCALE)

// shared memory float offsets
#define O_HIST  0                          // SEQ*HID : xw' -> r2 history
#define O_XS    (O_HIST + SEQ*HID)         // SEQ*INDIM
#define O_RING  (O_XS + SEQ*INDIM)         // RING*HID  r1 ring
#define O_PIR   (O_RING + RING*HID)        // RING*HID  pI ring (reduced + base2)
#define O_R2    (O_PIR + RING*HID)         // 2*HID     r2 double buffer
#define O_RS1   (O_R2 + 2*HID)             // HID
#define O_WFC   (O_RS1 + HID)              // OUTD*HID (scaled -2)
#define O_BFC   (O_WFC + OUTD*HID)         // 16
#define SM_FLOATS (O_BFC + 16)
#define SM_BYTES  (SM_FLOATS * 4)

typedef unsigned long long ull;

__device__ __forceinline__ ull ffma2(ull a, ull b, ull c) {
    ull d; asm("fma.rn.f32x2 %0, %1, %2, %3;" : "=l"(d) : "l"(a), "l"(b), "l"(c));
    return d;
}
__device__ __forceinline__ ull fadd2(ull a, ull b) {
    ull d; asm("add.rn.f32x2 %0, %1, %2;" : "=l"(d) : "l"(a), "l"(b));
    return d;
}
__device__ __forceinline__ float f2sum(ull a) {
    float2 f = *reinterpret_cast<float2*>(&a);
    return f.x + f.y;
}
__device__ __forceinline__ ull pack2(float x, float y) {
    ull r; asm("mov.b64 %0, {%1,%2};" : "=l"(r) : "f"(x), "f"(y));
    return r;
}
// r = 1/(e^{2s}+1) with input pre-scaled by 2/ln2; tanh(s) = 1 - 2r
__device__ __forceinline__ float sig_r(float in) {
    float e, r;
    asm("ex2.approx.f32 %0, %1;" : "=f"(e) : "f"(in));
    asm("rcp.approx.f32 %0, %1;" : "=f"(r) : "f"(e + 1.0f));
    return r;
}
#define BAR_L1() asm volatile("bar.sync 1, 64;" ::: "memory")
#define BAR_L2() asm volatile("bar.sync 2, 64;" ::: "memory")

// full 64-dot with seeded accumulator: seed + w.src, 4 chains, returns f32x2
__device__ __forceinline__ ull dot64_seed(const ull* __restrict__ w,
                                          const float* __restrict__ src,
                                          float seed) {
    const ulonglong2* hp = reinterpret_cast<const ulonglong2*>(src);
    ull a0 = 0ull, a1 = 0ull, a2 = 0ull;
    ull a3 = pack2(seed, 0.0f);
    #pragma unroll
    for (int q = 0; q < 8; ++q) {
        ulonglong2 u = hp[2*q], v = hp[2*q+1];
        a0 = ffma2(u.x, w[4*q+0], a0);
        a1 = ffma2(u.y, w[4*q+1], a1);
        a2 = ffma2(v.x, w[4*q+2], a2);
        a3 = ffma2(v.y, w[4*q+3], a3);
    }
    return fadd2(fadd2(a0, a1), fadd2(a2, a3));
}

// 32-long half dot: 8 LDS.128, 16 FFMA2 -> float
__device__ __forceinline__ float dot32h(const ull* __restrict__ w,
                                        const float* __restrict__ src) {
    const ulonglong2* hp = reinterpret_cast<const ulonglong2*>(src);
    ull a0 = 0ull, a1 = 0ull, a2 = 0ull, a3 = 0ull;
    #pragma unroll
    for (int q = 0; q < 4; ++q) {
        ulonglong2 u = hp[2*q], v = hp[2*q+1];
        a0 = ffma2(u.x, w[4*q+0], a0);
        a1 = ffma2(u.y, w[4*q+1], a1);
        a2 = ffma2(v.x, w[4*q+2], a2);
        a3 = ffma2(v.y, w[4*q+3], a3);
    }
    return f2sum(fadd2(fadd2(a0, a1), fadd2(a2, a3)));
}

__global__ __launch_bounds__(NTH, 1)
void rnn_motion_kernel(const float* __restrict__ x,
                       const float* __restrict__ Wih0, const float* __restrict__ Whh0,
                       const float* __restrict__ bih0, const float* __restrict__ bhh0,
                       const float* __restrict__ Wih1, const float* __restrict__ Whh1,
                       const float* __restrict__ bih1, const float* __restrict__ bhh1,
                       const float* __restrict__ Wfc,  const float* __restrict__ bfc_g,
                       float* __restrict__ out)
{
    extern __shared__ float sm[];
    float* hist = sm + O_HIST;
    float* xs   = sm + O_XS;
    float* ring = sm + O_RING;
    float* pir  = sm + O_PIR;
    float* r2b  = sm + O_R2;
    float* rs1  = sm + O_RS1;
    float* wfc  = sm + O_WFC;
    float* bfc  = sm + O_BFC;

    const int tid  = threadIdx.x;
    const int wid  = tid >> 5;
    const int lane = tid & 31;

    // ---- prologue A ----
    for (int e = tid; e < SEQ*INDIM; e += NTH) {
        int t = e / INDIM, k = e % INDIM;
        xs[e] = x[((size_t)t * BATCH + (BATCH - 1)) * INDIM + k];
    }
    for (int e = tid; e < OUTD*HID; e += NTH) wfc[e] = -2.0f * Wfc[e];
    if (tid < HID) {
        ring[(RING-1)*HID + tid] = 0.5f;    // r1(-1): h=0 <-> r=0.5
        r2b[HID + tid]           = 0.5f;    // r2(-1), parity 1
        const float4* p = reinterpret_cast<const float4*>(Whh0 + (size_t)tid * HID);
        float s = 0.f;
        #pragma unroll
        for (int q = 0; q < 16; ++q) { float4 v = p[q]; s += (v.x+v.y)+(v.z+v.w); }
        rs1[tid] = s;                       // rowsum(Whh0_i)
    }
    if (tid < OUTD) {                       // bfc'[o] = bfc + rowsum(Wfc_o)
        const float4* p = reinterpret_cast<const float4*>(Wfc + (size_t)tid * HID);
        float s = bfc_g[tid];
        #pragma unroll
        for (int q = 0; q < 16; ++q) { float4 v = p[q]; s += (v.x+v.y)+(v.z+v.w); }
        bfc[tid] = s;
    }
    __syncthreads();

    // ---- prologue B: xw'[t][i] = C*(x_t.Wih0_i + b_ih0 + b_hh0 + rowsum(Whh0_i)) ----
    {
        const int ii = tid & (HID-1);
        float wi[INDIM];
        #pragma unroll
        for (int k = 0; k < INDIM; ++k) wi[k] = CSCALE * Wih0[ii*INDIM + k];
        const float bb = CSCALE * (bih0[ii] + bhh0[ii] + rs1[ii]);
        for (int t = tid >> 6; t < SEQ; t += NTH/HID) {
            float s = bb;
            #pragma unroll
            for (int k = 0; k < INDIM; ++k) s += xs[t*INDIM + k] * wi[k];
            hist[t*HID + ii] = s;
        }
    }
    __syncthreads();

    // ==================== 3-stage pipelined scan ====================
    // wid 6,7: L1 (highest arbiter priority); wid 4,5: L2; wid 0-3: pI (lowest)
    if (wid >= 6) {
        // ===== L1 pair: unit i, 32 FFMA2/step, xw prefetched per block =====
        const int i = ((wid - 6) << 5) | lane;
        ull w1[32];
        {
            const float4* p = reinterpret_cast<const float4*>(Whh0 + (size_t)i * HID);
            #pragma unroll
            for (int q = 0; q < 16; ++q) {
                float4 v = p[q];
                w1[2*q]   = pack2(v.x*WSCALE, v.y*WSCALE);
                w1[2*q+1] = pack2(v.z*WSCALE, v.w*WSCALE);
            }
        }
        for (int m = 0; m < NPH; ++m) {
            if (m < NBLK) {
                const int t0 = m * BLKS;
                const float* src = ring + ((t0 - 1) & (RING-1)) * HID;
                float*       dst = ring + (t0 & (RING-1)) * HID;
                float xwreg[BLKS];                       // block prefetch (off-chain burst)
                {
                    const float* xwp = hist + t0*HID + i;
                    #pragma unroll
                    for (int j = 0; j < BLKS; ++j) xwreg[j] = xwp[j*HID];
                }
                #pragma unroll 2
                for (int j = 0; j < BLKS; ++j) {
                    ull s = dot64_seed(w1, src, xwreg[j]);
                    float r = sig_r(f2sum(s));
                    dst[i] = r;
                    BAR_L1();
                    src = dst; dst += HID;
                }
            }
            __syncthreads();
        }
    } else if (wid >= 4) {
        // ===== L2 pair: unit i, 32 FFMA2/step; pI (incl. base2) seeded =====
        const int i = ((wid - 4) << 5) | lane;
        ull wh[32];
        {
            const float4* p = reinterpret_cast<const float4*>(Whh1 + (size_t)i * HID);
            #pragma unroll
            for (int q = 0; q < 16; ++q) {
                float4 v = p[q];
                wh[2*q]   = pack2(v.x*WSCALE, v.y*WSCALE);
                wh[2*q+1] = pack2(v.z*WSCALE, v.w*WSCALE);
            }
        }
        for (int m = 0; m < NPH; ++m) {
            if (m >= 2) {
                const int s0 = (m - 2) * BLKS;          // even
                const float* pip = pir + (s0 & (RING-1)) * HID + i;
                float*       hw  = hist + s0*HID + i;
                #pragma unroll 1
                for (int jj = 0; jj < BLKS/2; ++jj) {
                    {   // s even: read r2 parity 1, write parity 0
                        float pi = *pip;                 // LDS issued first; covers seed
                        ull a = dot64_seed(wh, r2b + HID, pi);
                        float r = sig_r(f2sum(a));
                        r2b[i] = r; *hw = r;
                        BAR_L2();
                        pip += HID; hw += HID;
                    }
                    {   // s odd: read parity 0, write parity 1
                        float pi = *pip;
                        ull a = dot64_seed(wh, r2b, pi);
                        float r = sig_r(f2sum(a));
                        r2b[HID + i] = r; *hw = r;
                        BAR_L2();
                        pip += HID; hw += HID;
                    }
                }
            }
            __syncthreads();
        }
    } else {
        // ===== pI quad (wid 0-3): stores Wih1.r1 + base2; 1 block behind =====
        const int u = (wid << 4) | (lane & 15);         // unit
        const int h = lane >> 4;                        // input half
        const int off = h << 5;
        ull wi2[16];
        float rsHalf;                                   // rowsum(Wih1 half + Whh1 half)
        {
            const float4* p = reinterpret_cast<const float4*>(Wih1 + (size_t)u * HID + off);
            float s = 0.f;
            #pragma unroll
            for (int q = 0; q < 8; ++q) {
                float4 v = p[q];
                s += (v.x+v.y)+(v.z+v.w);
                wi2[2*q]   = pack2(v.x*WSCALE, v.y*WSCALE);
                wi2[2*q+1] = pack2(v.z*WSCALE, v.w*WSCALE);
            }
            const float4* p2 = reinterpret_cast<const float4*>(Whh1 + (size_t)u * HID + off);
            #pragma unroll
            for (int q = 0; q < 8; ++q) {
                float4 v = p2[q];
                s += (v.x+v.y)+(v.z+v.w);
            }
            rsHalf = s;
        }
        float rsFull = rsHalf + __shfl_xor_sync(0xffffffffu, rsHalf, 16);
        const float base2 = CSCALE * (bih1[u] + bhh1[u] + rsFull);
        for (int m = 0; m < NPH; ++m) {
            if (m >= 1 && m < NBLK + 1) {
                const int s0 = (m - 1) * BLKS;
                const float* rrow = ring + (s0 & (RING-1)) * HID + off;
                float*       pip  = pir  + (s0 & (RING-1)) * HID + u;
                #pragma unroll 2
                for (int j = 0; j < BLKS; ++j) {
                    float p = dot32h(wi2, rrow);
                    p += __shfl_xor_sync(0xffffffffu, p, 16);
                    *pip = p + base2;               // both halves write same value
                    rrow += HID; pip += HID;
                }
            }
            __syncthreads();
        }
    }
    __syncthreads();

    // ---- epilogue: out[t][o] = bfc'[o] + sum_k r2[t][k] * (-2*Wfc[o][k]) ----
    #pragma unroll
    for (int m = 0; m < SEQ/NTH; ++m) {
        const int t = tid + NTH * m;
        const float4* h4 = reinterpret_cast<const float4*>(hist + t*HID);
        #pragma unroll
        for (int o = 0; o < OUTD; ++o) {
            const float4* w4 = reinterpret_cast<const float4*>(wfc + o*HID);
            float s0 = bfc[o], s1 = 0.f, s2 = 0.f, s3 = 0.f;
            #pragma unroll
            for (int q = 0; q < HID/4; ++q) {
                float4 hv = h4[q], wv = w4[q];
                s0 = fmaf(hv.x, wv.x, s0);
                s1 = fmaf(hv.y, wv.y, s1);
                s2 = fmaf(hv.z, wv.z, s2);
                s3 = fmaf(hv.w, wv.w, s3);
            }
            out[t*OUTD + o] = (s0 + s1) + (s2 + s3);
        }
    }
}

extern "C" void kernel_launch(void* const* d_in, const int* in_sizes, int n_in,
                              void* d_out, int out_size) {
    (void)in_sizes; (void)n_in; (void)out_size;
    const float* x    = (const float*)d_in[0];
    const float* Wih0 = (const float*)d_in[1];
    const float* Whh0 = (const float*)d_in[2];
    const float* bih0 = (const float*)d_in[3];
    const float* bhh0 = (const float*)d_in[4];
    const float* Wih1 = (const float*)d_in[5];
    const float* Whh1 = (const float*)d_in[6];
    const float* bih1 = (const float*)d_in[7];
    const float* bhh1 = (const float*)d_in[8];
    const float* Wfc  = (const float*)d_in[9];
    const float* bfc  = (const float*)d_in[10];
    float* out = (float*)d_out;

    cudaFuncSetAttribute(rnn_motion_kernel,
                         cudaFuncAttributeMaxDynamicSharedMemorySize, SM_BYTES);
    rnn_motion_kernel<<<1, NTH, SM_BYTES>>>(
        x, Wih0, Whh0, bih0, bhh0, Wih1, Whh1, bih1, bhh1, Wfc, bfc, out);
}